// round 5
// baseline (speedup 1.0000x reference)
#include <cuda_runtime.h>
#include <math.h>

typedef unsigned long long u64;

#define NPTS 65536
#define KC   4096
#define DD   64
#define BM   128
#define BN   128
#define PAD  4
#define SROW (BM + PAD)      /* 132 floats: padded row stride for transposed tiles */
#define NTHREADS 256

/* ------- device scratch (no allocations allowed) ------- */
__device__ float g_e2[KC];
__device__ int   g_counts[KC];
__device__ float g_sqsum;
__device__ int   g_idx[NPTS];

/* ------- packed f32x2 helpers (sm_100+ PTX) ------- */
__device__ __forceinline__ u64 pack2(float lo, float hi) {
    u64 r; asm("mov.b64 %0, {%1, %2};" : "=l"(r) : "f"(lo), "f"(hi)); return r;
}
__device__ __forceinline__ void unpack2(u64 v, float &lo, float &hi) {
    asm("mov.b64 {%0, %1}, %2;" : "=f"(lo), "=f"(hi) : "l"(v));
}
__device__ __forceinline__ u64 ffma2(u64 a, u64 b, u64 c) {
    u64 d; asm("fma.rn.f32x2 %0, %1, %2, %3;" : "=l"(d) : "l"(a), "l"(b), "l"(c)); return d;
}

/* ------- K0: zero scratch (graph replays must be deterministic) ------- */
__global__ void k_zero() {
    int t = blockIdx.x * blockDim.x + threadIdx.x;
    if (t < KC) g_counts[t] = 0;
    if (t == 0) g_sqsum = 0.0f;
}

/* ------- K1: e2[k] = sum_d e[k][d]^2, sequential fp32 (no fma contraction) ------- */
__global__ void k_e2(const float* __restrict__ emb) {
    int k = blockIdx.x * blockDim.x + threadIdx.x;
    if (k >= KC) return;
    const float* row = emb + (size_t)k * DD;
    float s = 0.0f;
#pragma unroll
    for (int d = 0; d < DD; d++) s = __fadd_rn(s, __fmul_rn(row[d], row[d]));
    g_e2[k] = s;
}

/* ------- K2: fused distance GEMM + streaming argmin -------
 * dist[n][k] = fl( fl(z2[n] + e2[k]) - fl(2 * dot(z[n], e[k])) ), argmin tie -> lowest k.
 * Block tile: 128 rows x 128 codes, loop over K in chunks of 128.
 * Per-thread micro-tile 8x8, accumulators as f32x2 pairs (row pairs). */
extern __shared__ float smem_dyn[];

__global__ __launch_bounds__(NTHREADS)
void k_argmin(const float* __restrict__ z, const float* __restrict__ emb) {
    float* zs  = smem_dyn;               /* [DD][SROW] transposed z tile   */
    float* es  = zs + DD * SROW;         /* [DD][SROW] transposed emb tile */
    float* z2s = es + DD * SROW;         /* [BM] */
    float* e2s = z2s + BM;               /* [BN] */

    const int tid = threadIdx.x;
    const int n0  = blockIdx.x * BM;

    /* load z tile (coalesced global float4) and transpose into smem */
#pragma unroll
    for (int i = 0; i < 8; i++) {
        int lin = tid + i * NTHREADS;    /* 0..2047: 128 rows x 16 float4 */
        int r   = lin >> 4;
        int d4  = lin & 15;
        float4 v = *reinterpret_cast<const float4*>(z + (size_t)(n0 + r) * DD + d4 * 4);
        zs[(d4 * 4 + 0) * SROW + r] = v.x;
        zs[(d4 * 4 + 1) * SROW + r] = v.y;
        zs[(d4 * 4 + 2) * SROW + r] = v.z;
        zs[(d4 * 4 + 3) * SROW + r] = v.w;
    }
    /* z2 per row, sequential fp32 order matching k_e2 */
    if (tid < BM) {
        const float* row = z + (size_t)(n0 + tid) * DD;
        float s = 0.0f;
#pragma unroll
        for (int d = 0; d < DD; d++) s = __fadd_rn(s, __fmul_rn(row[d], row[d]));
        z2s[tid] = s;
    }
    __syncthreads();

    const int ty = tid >> 4;             /* 16 row-groups  */
    const int tx = tid & 15;             /* 16 code-groups */
    const int r0 = ty * 8;
    const int c0 = tx * 8;

    float z2r[8];
#pragma unroll
    for (int i = 0; i < 8; i++) z2r[i] = z2s[r0 + i];

    float best[8]; int bidx[8];
#pragma unroll
    for (int i = 0; i < 8; i++) { best[i] = 3.4e38f; bidx[i] = 0; }

    for (int k0 = 0; k0 < KC; k0 += BN) {
        /* load emb tile transposed */
#pragma unroll
        for (int i = 0; i < 8; i++) {
            int lin = tid + i * NTHREADS;
            int c   = lin >> 4;
            int d4  = lin & 15;
            float4 v = *reinterpret_cast<const float4*>(emb + (size_t)(k0 + c) * DD + d4 * 4);
            es[(d4 * 4 + 0) * SROW + c] = v.x;
            es[(d4 * 4 + 1) * SROW + c] = v.y;
            es[(d4 * 4 + 2) * SROW + c] = v.z;
            es[(d4 * 4 + 3) * SROW + c] = v.w;
        }
        if (tid < BN) e2s[tid] = g_e2[k0 + tid];
        __syncthreads();

        u64 acc[4][8];                    /* [row-pair][code] */
#pragma unroll
        for (int p = 0; p < 4; p++)
#pragma unroll
            for (int c = 0; c < 8; c++) acc[p][c] = 0ULL;

        const float* zp_base = zs + r0;
        const float* ep_base = es + c0;
#pragma unroll 8
        for (int d = 0; d < DD; d++) {
            const float* zrow = zp_base + d * SROW;
            const float* erow = ep_base + d * SROW;
            float4 za = *reinterpret_cast<const float4*>(zrow);
            float4 zb = *reinterpret_cast<const float4*>(zrow + 4);
            float4 ea = *reinterpret_cast<const float4*>(erow);
            float4 eb = *reinterpret_cast<const float4*>(erow + 4);
            u64 zp[4];
            zp[0] = pack2(za.x, za.y);
            zp[1] = pack2(za.z, za.w);
            zp[2] = pack2(zb.x, zb.y);
            zp[3] = pack2(zb.z, zb.w);
            float ef[8] = {ea.x, ea.y, ea.z, ea.w, eb.x, eb.y, eb.z, eb.w};
#pragma unroll
            for (int c = 0; c < 8; c++) {
                u64 ed = pack2(ef[c], ef[c]);
#pragma unroll
                for (int p = 0; p < 4; p++) acc[p][c] = ffma2(zp[p], ed, acc[p][c]);
            }
        }

        /* chunk epilogue: dist + running argmin (ascending code order, strict <) */
#pragma unroll
        for (int c = 0; c < 8; c++) {
            float e2v = e2s[c0 + c];
            int   gid = k0 + c0 + c;
#pragma unroll
            for (int p = 0; p < 4; p++) {
                float d0, d1; unpack2(acc[p][c], d0, d1);
                float A0 = __fadd_rn(z2r[2 * p],     e2v);
                float A1 = __fadd_rn(z2r[2 * p + 1], e2v);
                float x0 = __fsub_rn(A0, __fmul_rn(2.0f, d0));
                float x1 = __fsub_rn(A1, __fmul_rn(2.0f, d1));
                if (x0 < best[2 * p])     { best[2 * p]     = x0; bidx[2 * p]     = gid; }
                if (x1 < best[2 * p + 1]) { best[2 * p + 1] = x1; bidx[2 * p + 1] = gid; }
            }
        }
        __syncthreads();
    }

    /* reduce over the 16 code-group lanes (same ty = 16 consecutive lanes) */
#pragma unroll
    for (int off = 1; off < 16; off <<= 1) {
#pragma unroll
        for (int i = 0; i < 8; i++) {
            float ob = __shfl_xor_sync(0xffffffffu, best[i], off);
            int   oi = __shfl_xor_sync(0xffffffffu, bidx[i], off);
            if (ob < best[i] || (ob == best[i] && oi < bidx[i])) { best[i] = ob; bidx[i] = oi; }
        }
    }
    if (tx == 0) {
#pragma unroll
        for (int i = 0; i < 8; i++) g_idx[n0 + r0 + i] = bidx[i];
    }
}

/* ------- K3: gather z_q, write z_q_st + indices, accumulate sq-loss + counts ------- */
__global__ __launch_bounds__(256)
void k_gather(const float* __restrict__ z, const float* __restrict__ emb,
              float* __restrict__ out) {
    __shared__ float red[256];
    const int tid  = threadIdx.x;
    const int base = blockIdx.x * 512;                 /* 128 blocks x 512 rows */
    float acc = 0.0f;
    const size_t ND = (size_t)NPTS * DD;

    for (int i = 0; i < 32; i++) {
        int lin = tid + i * 256;                        /* 512 rows x 16 float4 */
        int r   = lin >> 4;
        int d4  = lin & 15;
        int n   = base + r;
        int idx = g_idx[n];
        float4 e4 = *reinterpret_cast<const float4*>(emb + (size_t)idx * DD + d4 * 4);
        float4 z4 = *reinterpret_cast<const float4*>(z + (size_t)n * DD + d4 * 4);
        *reinterpret_cast<float4*>(out + (size_t)n * DD + d4 * 4) = e4;
        float dx = e4.x - z4.x, dy = e4.y - z4.y, dz = e4.z - z4.z, dw = e4.w - z4.w;
        acc += dx * dx + dy * dy + dz * dz + dw * dw;
        if (d4 == 0) {
            atomicAdd(&g_counts[idx], 1);
            out[ND + 3 + n] = (float)idx;
        }
    }
    red[tid] = acc;
    __syncthreads();
    for (int s = 128; s > 0; s >>= 1) {
        if (tid < s) red[tid] += red[tid + s];
        __syncthreads();
    }
    if (tid == 0) atomicAdd(&g_sqsum, red[0]);
}

/* ------- K4: losses, perplexity, active codes ------- */
__global__ void k_final(float* __restrict__ out) {
    __shared__ float sH[256];
    __shared__ int   sA[256];
    int tid = threadIdx.x;
    float H = 0.0f; int active = 0;
    for (int i = tid; i < KC; i += 256) {
        float p = (float)g_counts[i] * (1.0f / 65536.0f);
        H += p * logf(p + 1e-10f);
        if (p > 0.0f) active++;
    }
    sH[tid] = H; sA[tid] = active;
    __syncthreads();
    for (int s = 128; s > 0; s >>= 1) {
        if (tid < s) { sH[tid] += sH[tid + s]; sA[tid] += sA[tid + s]; }
        __syncthreads();
    }
    if (tid == 0) {
        const size_t ND = (size_t)NPTS * DD;
        float mse = g_sqsum / (float)(NPTS * DD);       /* codebook == commit numerically */
        out[ND]     = __fadd_rn(mse, __fmul_rn(0.25f, mse));  /* vq_loss */
        out[ND + 1] = mse;                                    /* codebook_loss */
        out[ND + 2] = mse;                                    /* commit_loss */
        out[ND + 3 + NPTS] = expf(-sH[0]);                    /* perplexity */
        out[ND + 4 + NPTS] = (float)sA[0];                    /* active_codes */
    }
}

extern "C" void kernel_launch(void* const* d_in, const int* in_sizes, int n_in,
                              void* d_out, int out_size) {
    const float *z, *emb;
    if (in_sizes[0] == KC * DD) { emb = (const float*)d_in[0]; z = (const float*)d_in[1]; }
    else                        { z   = (const float*)d_in[0]; emb = (const float*)d_in[1]; }
    float* out = (float*)d_out;

    size_t smem = (size_t)(DD * SROW * 2 + BM + BN) * sizeof(float);   /* 68608 B */
    cudaFuncSetAttribute(k_argmin, cudaFuncAttributeMaxDynamicSharedMemorySize, (int)smem);

    k_zero <<<(KC + 255) / 256, 256>>>();
    k_e2   <<<(KC + 255) / 256, 256>>>(emb);
    k_argmin<<<NPTS / BM, NTHREADS, smem>>>(z, emb);
    k_gather<<<128, 256>>>(z, emb, out);
    k_final<<<1, 256>>>(out);
}